// round 7
// baseline (speedup 1.0000x reference)
#include <cuda_runtime.h>
#include <cstdint>

#define NC 256
#define NH 256
#define NW 256
#define NBOX 100
#define SLICES 8                       // writer blocks per channel
#define ROWS_PER_SLICE (NH / SLICES)   // 32
#define TILE_F4 (ROWS_PER_SLICE * NW / 4)   // 2048 float4 = 32KB per block

__device__ float4 g_coef[NC];          // A, B1, B2, D per channel

// ---------------------------------------------------------------------------
// Kernel 1: per-channel coefficients (one block per channel, fully parallel).
// nonzero(size=100, fill=0) == each selected box once + (100-cnt) copies of box 0.
// ---------------------------------------------------------------------------
__global__ __launch_bounds__(128)
void coef_kernel(const float* __restrict__ boxes,
                 const float* __restrict__ scores,
                 const float* __restrict__ feat) {
    __shared__ float4 red[128];
    __shared__ int    s_pc[4];
    const int tid = threadIdx.x;
    const int c   = blockIdx.x;

    int m = 0;
    if (tid < NBOX) m = (scores[tid] > 0.0f) ? 1 : 0;
    unsigned bal = __ballot_sync(0xffffffffu, m);
    if ((tid & 31) == 0) s_pc[tid >> 5] = __popc(bal);
    __syncthreads();
    const int cnt = s_pc[0] + s_pc[1] + s_pc[2] + s_pc[3];

    float4 acc = make_float4(0.f, 0.f, 0.f, 0.f);
    if (tid < NBOX) {
        const float4* b4 = (const float4*)(boxes + (size_t)tid * 24);
        float4 v0 = b4[0], v1 = b4[1], v2 = b4[2], v3 = b4[3], v4 = b4[4], v5 = b4[5];
        // corners are (x,y,z) triples: x at 0,3,..,21 ; y at 1,4,..,22
        float xs[8] = {v0.x, v0.w, v1.z, v2.y, v3.x, v3.w, v4.z, v5.y};
        float ys[8] = {v0.y, v1.x, v1.w, v2.z, v3.y, v4.x, v4.w, v5.z};
        float lx = xs[0], rx = xs[0], ly = ys[0], ry = ys[0];
        #pragma unroll
        for (int k = 1; k < 8; k++) {
            lx = fminf(lx, xs[k]); rx = fmaxf(rx, xs[k]);
            ly = fminf(ly, ys[k]); ry = fmaxf(ry, ys[k]);
        }
        float cx  = ((lx + rx) * 0.5f + 128.0f) / 160.0f;
        float cy  = ((ly + ry) * 0.5f + 128.0f) / 160.0f;
        float bev = ((ry - ly) / 160.0f) * ((rx - lx) / 160.0f);
        float a   = 1.0f / (2.0f * bev * bev);
        float r2  = cx * cx + cy * cy;

        // bilinear grid_sample (zero pad, align_corners=False)
        float ix = ((cx + 1.0f) * (float)NW - 1.0f) * 0.5f;
        float iy = ((cy + 1.0f) * (float)NH - 1.0f) * 0.5f;
        float x0f = floorf(ix), y0f = floorf(iy);
        float wx1 = ix - x0f, wx0 = 1.0f - wx1;
        float wy1 = iy - y0f, wy0 = 1.0f - wy1;
        int x0 = (int)x0f, y0 = (int)y0f, x1 = x0 + 1, y1 = y0 + 1;
        bool vx0 = (x0 >= 0 && x0 < NW), vx1 = (x1 >= 0 && x1 < NW);
        bool vy0 = (y0 >= 0 && y0 < NH), vy1 = (y1 >= 0 && y1 < NH);
        int px0 = min(max(x0, 0), NW - 1), px1 = min(max(x1, 0), NW - 1);
        int py0 = min(max(y0, 0), NH - 1), py1 = min(max(y1, 0), NH - 1);
        float w00 = (vx0 && vy0) ? wx0 * wy0 : 0.0f;
        float w10 = (vx1 && vy0) ? wx1 * wy0 : 0.0f;
        float w01 = (vx0 && vy1) ? wx0 * wy1 : 0.0f;
        float w11 = (vx1 && vy1) ? wx1 * wy1 : 0.0f;

        const float* fc = feat + (size_t)c * NH * NW;
        float v = w00 * __ldg(fc + py0 * NW + px0)
                + w10 * __ldg(fc + py0 * NW + px1)
                + w01 * __ldg(fc + py1 * NW + px0)
                + w11 * __ldg(fc + py1 * NW + px1);

        float mult = (tid == 0) ? (float)(m + NBOX - cnt) : (float)m;
        float ta = v * a * mult;
        acc = make_float4(ta, ta * cx, ta * cy, ta * r2);
    }
    red[tid] = acc;
    __syncthreads();
    #pragma unroll
    for (int s = 64; s > 0; s >>= 1) {
        if (tid < s) {
            float4 u = red[tid], v = red[tid + s];
            red[tid] = make_float4(u.x + v.x, u.y + v.y, u.z + v.z, u.w + v.w);
        }
        __syncthreads();
    }
    if (tid == 0) {
        const float inv = 1.0f / (float)NBOX;
        float4 r = red[0];
        g_coef[c] = make_float4(r.x * inv, 2.0f * r.y * inv, 2.0f * r.z * inv, r.w * inv);
    }
}

// ---------------------------------------------------------------------------
// Kernel 2: writer via bulk-async store. Compute 32KB tile into SMEM (STS.128),
// then ONE cp.async.bulk shared->global per block. Stores bypass per-warp LSU
// issue and ride the TMA/LTS path at the chip cap.
//   out[c,h,w] = w*(w*A - B1) + h*(h*A - B2) + D
// ---------------------------------------------------------------------------
__global__ __launch_bounds__(256)
void out_kernel(float4* __restrict__ out) {
    __shared__ alignas(128) float4 buf[TILE_F4];   // 32 KB
    const int tid   = threadIdx.x;
    const int c     = blockIdx.x >> 3;
    const int slice = blockIdx.x & 7;

    const float4 k4 = __ldg(&g_coef[c]);
    const float A = k4.x, B1 = k4.y, B2 = k4.z, D = k4.w;

    const float w0 = (float)((tid & 63) * 4);
    const float pw0 = (w0       ) * fmaf(w0,        A, -B1);
    const float pw1 = (w0 + 1.f ) * fmaf(w0 + 1.f,  A, -B1);
    const float pw2 = (w0 + 2.f ) * fmaf(w0 + 2.f,  A, -B1);
    const float pw3 = (w0 + 3.f ) * fmaf(w0 + 3.f,  A, -B1);

    #pragma unroll
    for (int k = 0; k < TILE_F4 / 256; k++) {   // 8 iters
        int   i    = k * 256 + tid;
        float hf   = (float)(slice * ROWS_PER_SLICE + (i >> 6));
        float base = fmaf(hf, fmaf(hf, A, -B2), D);
        buf[i] = make_float4(pw0 + base, pw1 + base, pw2 + base, pw3 + base);
    }
    __syncthreads();

    if (tid == 0) {
        asm volatile("fence.proxy.async.shared::cta;" ::: "memory");
        uint32_t saddr = (uint32_t)__cvta_generic_to_shared(buf);
        float4*  gdst  = out + (size_t)blockIdx.x * TILE_F4;
        asm volatile(
            "cp.async.bulk.global.shared::cta.bulk_group [%0], [%1], %2;"
            :: "l"(gdst), "r"(saddr), "n"(TILE_F4 * 16) : "memory");
        asm volatile("cp.async.bulk.commit_group;" ::: "memory");
        asm volatile("cp.async.bulk.wait_group 0;" ::: "memory");
    }
}

// ---------------------------------------------------------------------------
extern "C" void kernel_launch(void* const* d_in, const int* in_sizes, int n_in,
                              void* d_out, int out_size) {
    const float* boxes  = (const float*)d_in[0];   // [100,8,3]
    const float* scores = (const float*)d_in[1];   // [100]
    const float* feat   = (const float*)d_in[2];   // [1,256,256,256]

    coef_kernel<<<NC, 128>>>(boxes, scores, feat);
    out_kernel<<<NC * SLICES, 256>>>((float4*)d_out);
    (void)in_sizes; (void)n_in; (void)out_size;
}

// round 8
// speedup vs baseline: 1.0258x; 1.0258x over previous
#include <cuda_runtime.h>
#include <cstdint>

#define NC 256
#define NH 256
#define NW 256
#define NBOX 100
#define SLICES 4                       // writer blocks per channel
#define ROWS_PER_SLICE (NH / SLICES)   // 64
#define TILE_F4 (ROWS_PER_SLICE * NW / 4)   // 4096 float4 per block

__device__ float4 g_coef[NC];          // A, B1, B2, D per channel

// ---------------------------------------------------------------------------
// Kernel 1: per-channel coefficients (one block per channel, fully parallel).
// nonzero(size=100, fill=0) == each selected box once + (100-cnt) copies of box 0.
// Triggers dependent launch as soon as its coef is globally visible.
// ---------------------------------------------------------------------------
__global__ __launch_bounds__(128)
void coef_kernel(const float* __restrict__ boxes,
                 const float* __restrict__ scores,
                 const float* __restrict__ feat) {
    __shared__ float4 red[128];
    __shared__ int    s_pc[4];
    const int tid = threadIdx.x;
    const int c   = blockIdx.x;

    int m = 0;
    if (tid < NBOX) m = (scores[tid] > 0.0f) ? 1 : 0;
    unsigned bal = __ballot_sync(0xffffffffu, m);
    if ((tid & 31) == 0) s_pc[tid >> 5] = __popc(bal);
    __syncthreads();
    const int cnt = s_pc[0] + s_pc[1] + s_pc[2] + s_pc[3];

    float4 acc = make_float4(0.f, 0.f, 0.f, 0.f);
    if (tid < NBOX) {
        const float4* b4 = (const float4*)(boxes + (size_t)tid * 24);
        float4 v0 = b4[0], v1 = b4[1], v2 = b4[2], v3 = b4[3], v4 = b4[4], v5 = b4[5];
        // corners are (x,y,z) triples: x at 0,3,..,21 ; y at 1,4,..,22
        float xs[8] = {v0.x, v0.w, v1.z, v2.y, v3.x, v3.w, v4.z, v5.y};
        float ys[8] = {v0.y, v1.x, v1.w, v2.z, v3.y, v4.x, v4.w, v5.z};
        float lx = xs[0], rx = xs[0], ly = ys[0], ry = ys[0];
        #pragma unroll
        for (int k = 1; k < 8; k++) {
            lx = fminf(lx, xs[k]); rx = fmaxf(rx, xs[k]);
            ly = fminf(ly, ys[k]); ry = fmaxf(ry, ys[k]);
        }
        float cx  = ((lx + rx) * 0.5f + 128.0f) / 160.0f;
        float cy  = ((ly + ry) * 0.5f + 128.0f) / 160.0f;
        float bev = ((ry - ly) / 160.0f) * ((rx - lx) / 160.0f);
        float a   = 1.0f / (2.0f * bev * bev);
        float r2  = cx * cx + cy * cy;

        // bilinear grid_sample (zero pad, align_corners=False)
        float ix = ((cx + 1.0f) * (float)NW - 1.0f) * 0.5f;
        float iy = ((cy + 1.0f) * (float)NH - 1.0f) * 0.5f;
        float x0f = floorf(ix), y0f = floorf(iy);
        float wx1 = ix - x0f, wx0 = 1.0f - wx1;
        float wy1 = iy - y0f, wy0 = 1.0f - wy1;
        int x0 = (int)x0f, y0 = (int)y0f, x1 = x0 + 1, y1 = y0 + 1;
        bool vx0 = (x0 >= 0 && x0 < NW), vx1 = (x1 >= 0 && x1 < NW);
        bool vy0 = (y0 >= 0 && y0 < NH), vy1 = (y1 >= 0 && y1 < NH);
        int px0 = min(max(x0, 0), NW - 1), px1 = min(max(x1, 0), NW - 1);
        int py0 = min(max(y0, 0), NH - 1), py1 = min(max(y1, 0), NH - 1);
        float w00 = (vx0 && vy0) ? wx0 * wy0 : 0.0f;
        float w10 = (vx1 && vy0) ? wx1 * wy0 : 0.0f;
        float w01 = (vx0 && vy1) ? wx0 * wy1 : 0.0f;
        float w11 = (vx1 && vy1) ? wx1 * wy1 : 0.0f;

        const float* fc = feat + (size_t)c * NH * NW;
        float v = w00 * __ldg(fc + py0 * NW + px0)
                + w10 * __ldg(fc + py0 * NW + px1)
                + w01 * __ldg(fc + py1 * NW + px0)
                + w11 * __ldg(fc + py1 * NW + px1);

        float mult = (tid == 0) ? (float)(m + NBOX - cnt) : (float)m;
        float ta = v * a * mult;
        acc = make_float4(ta, ta * cx, ta * cy, ta * r2);
    }
    red[tid] = acc;
    __syncthreads();
    #pragma unroll
    for (int s = 64; s > 0; s >>= 1) {
        if (tid < s) {
            float4 u = red[tid], v = red[tid + s];
            red[tid] = make_float4(u.x + v.x, u.y + v.y, u.z + v.z, u.w + v.w);
        }
        __syncthreads();
    }
    if (tid == 0) {
        const float inv = 1.0f / (float)NBOX;
        float4 r = red[0];
        g_coef[c] = make_float4(r.x * inv, 2.0f * r.y * inv, 2.0f * r.z * inv, r.w * inv);
        __threadfence();   // make g_coef visible before signaling dependents
    }
    __syncthreads();
    asm volatile("griddepcontrol.launch_dependents;");
}

// ---------------------------------------------------------------------------
// Kernel 2: pure streaming STG.128 writer (the L2-write-cap path).
// grid = 1024 blocks -> single wave on 148 SMs (8 blocks/SM capacity).
//   out[c,h,w] = w*(w*A - B1) + h*(h*A - B2) + D
// ---------------------------------------------------------------------------
__global__ __launch_bounds__(256)
void out_kernel(float4* __restrict__ out) {
    asm volatile("griddepcontrol.wait;" ::: "memory");
    const int tid   = threadIdx.x;
    const int c     = blockIdx.x >> 2;
    const int slice = blockIdx.x & 3;

    const float4 k4 = __ldg(&g_coef[c]);
    const float A = k4.x, B1 = k4.y, B2 = k4.z, D = k4.w;

    float4* oc = out + (size_t)c * (NH * NW / 4) + slice * TILE_F4;
    const float w0 = (float)((tid & 63) * 4);
    // w-polynomial invariant across all rows this thread touches
    const float pw0 = (w0      ) * fmaf(w0,       A, -B1);
    const float pw1 = (w0 + 1.f) * fmaf(w0 + 1.f, A, -B1);
    const float pw2 = (w0 + 2.f) * fmaf(w0 + 2.f, A, -B1);
    const float pw3 = (w0 + 3.f) * fmaf(w0 + 3.f, A, -B1);

    #pragma unroll
    for (int k = 0; k < TILE_F4 / 256; k++) {   // 16 iters
        int   i    = k * 256 + tid;
        float hf   = (float)(slice * ROWS_PER_SLICE + (i >> 6));
        float base = fmaf(hf, fmaf(hf, A, -B2), D);
        oc[i] = make_float4(pw0 + base, pw1 + base, pw2 + base, pw3 + base);
    }
}

// ---------------------------------------------------------------------------
extern "C" void kernel_launch(void* const* d_in, const int* in_sizes, int n_in,
                              void* d_out, int out_size) {
    const float* boxes  = (const float*)d_in[0];   // [100,8,3]
    const float* scores = (const float*)d_in[1];   // [100]
    const float* feat   = (const float*)d_in[2];   // [1,256,256,256]

    coef_kernel<<<NC, 128>>>(boxes, scores, feat);

    // Programmatic dependent launch: writer starts while coef drains;
    // griddepcontrol.wait in the writer orders it after the trigger.
    cudaLaunchConfig_t cfg = {};
    cfg.gridDim  = dim3(NC * SLICES);
    cfg.blockDim = dim3(256);
    cfg.dynamicSmemBytes = 0;
    cfg.stream = 0;
    cudaLaunchAttribute attr[1];
    attr[0].id = cudaLaunchAttributeProgrammaticStreamSerialization;
    attr[0].val.programmaticStreamSerializationAllowed = 1;
    cfg.attrs = attr;
    cfg.numAttrs = 1;
    cudaLaunchKernelEx(&cfg, out_kernel, (float4*)d_out);

    (void)in_sizes; (void)n_in; (void)out_size;
}

// round 9
// speedup vs baseline: 1.0590x; 1.0324x over previous
#include <cuda_runtime.h>
#include <cstdint>

#define NC 256
#define NH 256
#define NW 256
#define NBOX 100
#define SLICES 8                       // writer blocks per channel (best measured: 2048 blocks)
#define ROWS_PER_SLICE (NH / SLICES)   // 32
#define TILE_F4 (ROWS_PER_SLICE * NW / 4)   // 2048 float4 per block

__device__ float4 g_coef[NC];          // A, B1, B2, D per channel

// ---------------------------------------------------------------------------
// Kernel 1: per-channel coefficients (one block per channel, fully parallel).
// nonzero(size=100, fill=0) == each selected box once + (100-cnt) copies of box 0.
// Fires the PDL trigger as soon as its coef is globally visible.
// ---------------------------------------------------------------------------
__global__ __launch_bounds__(128)
void coef_kernel(const float* __restrict__ boxes,
                 const float* __restrict__ scores,
                 const float* __restrict__ feat) {
    __shared__ float4 red[128];
    __shared__ int    s_pc[4];
    const int tid = threadIdx.x;
    const int c   = blockIdx.x;

    int m = 0;
    if (tid < NBOX) m = (scores[tid] > 0.0f) ? 1 : 0;
    unsigned bal = __ballot_sync(0xffffffffu, m);
    if ((tid & 31) == 0) s_pc[tid >> 5] = __popc(bal);
    __syncthreads();
    const int cnt = s_pc[0] + s_pc[1] + s_pc[2] + s_pc[3];

    float4 acc = make_float4(0.f, 0.f, 0.f, 0.f);
    if (tid < NBOX) {
        const float4* b4 = (const float4*)(boxes + (size_t)tid * 24);
        float4 v0 = b4[0], v1 = b4[1], v2 = b4[2], v3 = b4[3], v4 = b4[4], v5 = b4[5];
        // corners are (x,y,z) triples: x at 0,3,..,21 ; y at 1,4,..,22
        float xs[8] = {v0.x, v0.w, v1.z, v2.y, v3.x, v3.w, v4.z, v5.y};
        float ys[8] = {v0.y, v1.x, v1.w, v2.z, v3.y, v4.x, v4.w, v5.z};
        float lx = xs[0], rx = xs[0], ly = ys[0], ry = ys[0];
        #pragma unroll
        for (int k = 1; k < 8; k++) {
            lx = fminf(lx, xs[k]); rx = fmaxf(rx, xs[k]);
            ly = fminf(ly, ys[k]); ry = fmaxf(ry, ys[k]);
        }
        float cx  = ((lx + rx) * 0.5f + 128.0f) / 160.0f;
        float cy  = ((ly + ry) * 0.5f + 128.0f) / 160.0f;
        float bev = ((ry - ly) / 160.0f) * ((rx - lx) / 160.0f);
        float a   = 1.0f / (2.0f * bev * bev);
        float r2  = cx * cx + cy * cy;

        // bilinear grid_sample (zero pad, align_corners=False)
        float ix = ((cx + 1.0f) * (float)NW - 1.0f) * 0.5f;
        float iy = ((cy + 1.0f) * (float)NH - 1.0f) * 0.5f;
        float x0f = floorf(ix), y0f = floorf(iy);
        float wx1 = ix - x0f, wx0 = 1.0f - wx1;
        float wy1 = iy - y0f, wy0 = 1.0f - wy1;
        int x0 = (int)x0f, y0 = (int)y0f, x1 = x0 + 1, y1 = y0 + 1;
        bool vx0 = (x0 >= 0 && x0 < NW), vx1 = (x1 >= 0 && x1 < NW);
        bool vy0 = (y0 >= 0 && y0 < NH), vy1 = (y1 >= 0 && y1 < NH);
        int px0 = min(max(x0, 0), NW - 1), px1 = min(max(x1, 0), NW - 1);
        int py0 = min(max(y0, 0), NH - 1), py1 = min(max(y1, 0), NH - 1);
        float w00 = (vx0 && vy0) ? wx0 * wy0 : 0.0f;
        float w10 = (vx1 && vy0) ? wx1 * wy0 : 0.0f;
        float w01 = (vx0 && vy1) ? wx0 * wy1 : 0.0f;
        float w11 = (vx1 && vy1) ? wx1 * wy1 : 0.0f;

        const float* fc = feat + (size_t)c * NH * NW;
        float v = w00 * __ldg(fc + py0 * NW + px0)
                + w10 * __ldg(fc + py0 * NW + px1)
                + w01 * __ldg(fc + py1 * NW + px0)
                + w11 * __ldg(fc + py1 * NW + px1);

        float mult = (tid == 0) ? (float)(m + NBOX - cnt) : (float)m;
        float ta = v * a * mult;
        acc = make_float4(ta, ta * cx, ta * cy, ta * r2);
    }
    red[tid] = acc;
    __syncthreads();
    #pragma unroll
    for (int s = 64; s > 0; s >>= 1) {
        if (tid < s) {
            float4 u = red[tid], v = red[tid + s];
            red[tid] = make_float4(u.x + v.x, u.y + v.y, u.z + v.z, u.w + v.w);
        }
        __syncthreads();
    }
    if (tid == 0) {
        const float inv = 1.0f / (float)NBOX;
        float4 r = red[0];
        g_coef[c] = make_float4(r.x * inv, 2.0f * r.y * inv, 2.0f * r.z * inv, r.w * inv);
        __threadfence();   // g_coef visible before dependents may read it
    }
    __syncthreads();
    asm volatile("griddepcontrol.launch_dependents;");
}

// ---------------------------------------------------------------------------
// Kernel 2: pure streaming STG.128 writer — at the L2 write-port cap.
// Best measured config: 2048 blocks x 256 threads, 8 STG.128 per thread.
//   out[c,h,w] = w*(w*A - B1) + h*(h*A - B2) + D
// ---------------------------------------------------------------------------
__global__ __launch_bounds__(256)
void out_kernel(float4* __restrict__ out) {
    asm volatile("griddepcontrol.wait;" ::: "memory");
    const int tid   = threadIdx.x;
    const int c     = blockIdx.x >> 3;
    const int slice = blockIdx.x & 7;

    const float4 k4 = __ldg(&g_coef[c]);
    const float A = k4.x, B1 = k4.y, B2 = k4.z, D = k4.w;

    float4* oc = out + (size_t)blockIdx.x * TILE_F4;
    const float w0 = (float)((tid & 63) * 4);
    // w-polynomial invariant across the rows this thread touches
    const float pw0 = (w0      ) * fmaf(w0,       A, -B1);
    const float pw1 = (w0 + 1.f) * fmaf(w0 + 1.f, A, -B1);
    const float pw2 = (w0 + 2.f) * fmaf(w0 + 2.f, A, -B1);
    const float pw3 = (w0 + 3.f) * fmaf(w0 + 3.f, A, -B1);

    #pragma unroll
    for (int k = 0; k < TILE_F4 / 256; k++) {   // 8 iters
        int   i    = k * 256 + tid;
        float hf   = (float)(slice * ROWS_PER_SLICE + (i >> 6));
        float base = fmaf(hf, fmaf(hf, A, -B2), D);
        oc[i] = make_float4(pw0 + base, pw1 + base, pw2 + base, pw3 + base);
    }
}

// ---------------------------------------------------------------------------
extern "C" void kernel_launch(void* const* d_in, const int* in_sizes, int n_in,
                              void* d_out, int out_size) {
    const float* boxes  = (const float*)d_in[0];   // [100,8,3]
    const float* scores = (const float*)d_in[1];   // [100]
    const float* feat   = (const float*)d_in[2];   // [1,256,256,256]

    coef_kernel<<<NC, 128>>>(boxes, scores, feat);

    // Programmatic dependent launch: writer spins up while coef drains.
    cudaLaunchConfig_t cfg = {};
    cfg.gridDim  = dim3(NC * SLICES);   // 2048 blocks (best writer config)
    cfg.blockDim = dim3(256);
    cfg.dynamicSmemBytes = 0;
    cfg.stream = 0;
    cudaLaunchAttribute attr[1];
    attr[0].id = cudaLaunchAttributeProgrammaticStreamSerialization;
    attr[0].val.programmaticStreamSerializationAllowed = 1;
    cfg.attrs = attr;
    cfg.numAttrs = 1;
    cudaLaunchKernelEx(&cfg, out_kernel, (float4*)d_out);

    (void)in_sizes; (void)n_in; (void)out_size;
}